// round 5
// baseline (speedup 1.0000x reference)
#include <cuda_runtime.h>
#include <cuda_bf16.h>
#include <cstdint>

// Greedy CTC decode, single fused kernel:
//   emission: [T, V=128] fp32
//   out (fp32, 3*T): [ idx(0:T) | keep(T:2T) | path_score(2T:3T) ]
//
// Warp handles 8 consecutive rows: 8 front-batched LDG.128 (MLP=8), then
// per-row warp argmax via fmono + REDUX + ballot (first-occurrence).
// Dedup is in-register; cross-warp prev flows through smem guarded by
// PAIRWISE named barriers (bar.arrive/bar.sync, count=64) so warp w waits
// only on warp w-1, not the whole block. Warp 0 loads row base-1 itself
// (block>0) for an exact cross-block prev -> no fixup pass needed.

#define V 128
#define BLANK 0
#define WARPS_PER_BLOCK 8
#define ROWS_PER_WARP 8
#define ROWS_PER_BLOCK (WARPS_PER_BLOCK * ROWS_PER_WARP)   // 64
#define FULL_MASK 0xFFFFFFFFu

// Order-preserving fp32 bits -> u32 map and inverse.
__device__ __forceinline__ unsigned fmono(float f) {
    unsigned b = __float_as_uint(f);
    return b ^ ((unsigned)((int)b >> 31) | 0x80000000u);
}
__device__ __forceinline__ float funmono(unsigned u) {
    unsigned b = u ^ ((unsigned)((int)(~u) >> 31) | 0x80000000u);
    return __uint_as_float(b);
}

// Warp argmax of one row held as lane-local float4. Returns (idx, max) to all lanes.
__device__ __forceinline__ void warp_row_argmax(const float4 v, int lane,
                                                float& o_idx, float& o_max)
{
    float best = v.x; int bi = lane * 4;
    if (v.y > best) { best = v.y; bi = lane * 4 + 1; }
    if (v.z > best) { best = v.z; bi = lane * 4 + 2; }
    if (v.w > best) { best = v.w; bi = lane * 4 + 3; }

    unsigned key  = fmono(best);
    unsigned wmax = __reduce_max_sync(FULL_MASK, key);
    unsigned ball = __ballot_sync(FULL_MASK, key == wmax);
    int src  = __ffs(ball) - 1;                 // lowest lane = lowest column
    o_idx = (float)__shfl_sync(FULL_MASK, bi, src);
    o_max = funmono(wmax);
}

__global__ void __launch_bounds__(WARPS_PER_BLOCK * 32)
ctc_fused_kernel(const float* __restrict__ em,
                 float* __restrict__ out_idx,
                 float* __restrict__ out_keep,
                 float* __restrict__ out_score)
{
    __shared__ float s_last[WARPS_PER_BLOCK];   // last idx of each warp's tile

    const int lane = threadIdx.x & 31;
    const int warp = threadIdx.x >> 5;
    const int base = blockIdx.x * ROWS_PER_BLOCK + warp * ROWS_PER_WARP;

    // Front-batched loads: 8 independent LDG.128, 4KB contiguous per warp.
    float4 v[ROWS_PER_WARP];
    #pragma unroll
    for (int k = 0; k < ROWS_PER_WARP; k++) {
        v[k] = reinterpret_cast<const float4*>(em + (size_t)(base + k) * V)[lane];
    }

    // Warp 0 also loads the row preceding the block for an exact prev.
    float4 ev;
    const bool has_prev_row = (warp == 0) && (blockIdx.x > 0);
    if (has_prev_row) {
        ev = reinterpret_cast<const float4*>(em + (size_t)(base - 1) * V)[lane];
    }

    float res_idx[ROWS_PER_WARP];
    float res_max[ROWS_PER_WARP];
    #pragma unroll
    for (int k = 0; k < ROWS_PER_WARP; k++) {
        warp_row_argmax(v[k], lane, res_idx[k], res_max[k]);
    }

    // Publish this warp's last idx for warp+1; pairwise sync, not block-wide.
    if (lane == 0) s_last[warp] = res_idx[ROWS_PER_WARP - 1];
    __threadfence_block();
    if (warp < WARPS_PER_BLOCK - 1) {
        int bid = warp + 1;
        asm volatile("bar.arrive %0, %1;" :: "r"(bid), "r"(64) : "memory");
    }

    // prev for this warp's row 0.
    float prev;
    if (warp > 0) {
        int bid = warp;
        asm volatile("bar.sync %0, %1;" :: "r"(bid), "r"(64) : "memory");
        prev = s_last[warp - 1];
    } else if (has_prev_row) {
        float pi, pm;
        warp_row_argmax(ev, lane, pi, pm);
        prev = pi;
    } else {
        prev = -1.0f;   // t = 0
    }

    // In-register dedup (warp-uniform values).
    float kp[ROWS_PER_WARP], sc[ROWS_PER_WARP];
    #pragma unroll
    for (int k = 0; k < ROWS_PER_WARP; k++) {
        float cur = res_idx[k];
        bool keep = (cur != prev) && (cur != (float)BLANK);
        kp[k] = keep ? 1.0f : 0.0f;
        sc[k] = keep ? res_max[k] : 0.0f;
        prev = cur;
    }

    if (lane == 0) {
        // base is a multiple of 8 -> 16B-aligned float4 stores
        reinterpret_cast<float4*>(out_idx + base)[0] =
            make_float4(res_idx[0], res_idx[1], res_idx[2], res_idx[3]);
        reinterpret_cast<float4*>(out_idx + base)[1] =
            make_float4(res_idx[4], res_idx[5], res_idx[6], res_idx[7]);
        reinterpret_cast<float4*>(out_keep + base)[0] =
            make_float4(kp[0], kp[1], kp[2], kp[3]);
        reinterpret_cast<float4*>(out_keep + base)[1] =
            make_float4(kp[4], kp[5], kp[6], kp[7]);
        reinterpret_cast<float4*>(out_score + base)[0] =
            make_float4(sc[0], sc[1], sc[2], sc[3]);
        reinterpret_cast<float4*>(out_score + base)[1] =
            make_float4(sc[4], sc[5], sc[6], sc[7]);
    }
}

extern "C" void kernel_launch(void* const* d_in, const int* in_sizes, int n_in,
                              void* d_out, int out_size)
{
    const float* em = (const float*)d_in[0];
    float* out = (float*)d_out;

    const int rows = in_sizes[0] / V;            // T = 1048576 (divisible by 64)
    float* out_idx   = out;                      // [0:T)
    float* out_keep  = out + rows;               // [T:2T)
    float* out_score = out + 2 * (size_t)rows;   // [2T:3T)

    dim3 block(WARPS_PER_BLOCK * 32);
    dim3 grid(rows / ROWS_PER_BLOCK);            // exact
    ctc_fused_kernel<<<grid, block>>>(em, out_idx, out_keep, out_score);
}

// round 6
// speedup vs baseline: 1.1000x; 1.1000x over previous
#include <cuda_runtime.h>
#include <cuda_bf16.h>
#include <cstdint>

// Greedy CTC decode (split, R2 structure protected):
//   emission: [T, V=128] fp32
//   out (fp32, 3*T): [ idx(0:T) | keep(T:2T) | path_score(2T:3T) ]
//
// Kernel 1: warp handles 8 consecutive rows; 8 front-batched LDG.128 (MLP=8).
//           Per-row warp argmax with exactly 2 REDUX collectives:
//           max over monotone key, then min over tied lanes' indices
//           (= first occurrence, matching jnp.argmax).
// Kernel 2: vectorized dedup; prev comes from __shfl_up (lane 0 only loads).

#define V 128
#define BLANK 0
#define WARPS_PER_BLOCK 8
#define ROWS_PER_WARP 8
#define ROWS_PER_BLOCK (WARPS_PER_BLOCK * ROWS_PER_WARP)   // 64
#define FULL_MASK 0xFFFFFFFFu

// Order-preserving fp32 bits -> u32 map and inverse.
__device__ __forceinline__ unsigned fmono(float f) {
    unsigned b = __float_as_uint(f);
    return b ^ ((unsigned)((int)b >> 31) | 0x80000000u);
}
__device__ __forceinline__ float funmono(unsigned u) {
    unsigned b = u ^ ((unsigned)((int)(~u) >> 31) | 0x80000000u);
    return __uint_as_float(b);
}

__global__ void __launch_bounds__(WARPS_PER_BLOCK * 32)
ctc_argmax_kernel(const float* __restrict__ em,
                  float* __restrict__ out_idx,
                  float* __restrict__ out_max,
                  int rows)
{
    const int lane = threadIdx.x & 31;
    const int base = (blockIdx.x * WARPS_PER_BLOCK + (threadIdx.x >> 5)) * ROWS_PER_WARP;
    if (base >= rows) return;

    // Front-batched loads: 8 independent LDG.128, 4KB contiguous per warp.
    float4 v[ROWS_PER_WARP];
    #pragma unroll
    for (int k = 0; k < ROWS_PER_WARP; k++) {
        v[k] = reinterpret_cast<const float4*>(em + (size_t)(base + k) * V)[lane];
    }

    float res_idx[ROWS_PER_WARP];
    float res_max[ROWS_PER_WARP];

    #pragma unroll
    for (int k = 0; k < ROWS_PER_WARP; k++) {
        // Local argmax over this lane's 4 columns (strict > keeps earliest).
        float best = v[k].x; int bi = lane * 4;
        if (v[k].y > best) { best = v[k].y; bi = lane * 4 + 1; }
        if (v[k].z > best) { best = v[k].z; bi = lane * 4 + 2; }
        if (v[k].w > best) { best = v[k].w; bi = lane * 4 + 3; }

        unsigned key  = fmono(best);
        unsigned wmax = __reduce_max_sync(FULL_MASK, key);
        unsigned cand = (key == wmax) ? (unsigned)bi : 0x7FFFFFFFu;
        unsigned widx = __reduce_min_sync(FULL_MASK, cand);  // lowest col of ties

        res_idx[k] = (float)widx;
        res_max[k] = funmono(wmax);
    }

    if (lane == 0) {
        // base is a multiple of 8 -> 16B-aligned float4 stores
        reinterpret_cast<float4*>(out_idx + base)[0] =
            make_float4(res_idx[0], res_idx[1], res_idx[2], res_idx[3]);
        reinterpret_cast<float4*>(out_idx + base)[1] =
            make_float4(res_idx[4], res_idx[5], res_idx[6], res_idx[7]);
        reinterpret_cast<float4*>(out_max + base)[0] =
            make_float4(res_max[0], res_max[1], res_max[2], res_max[3]);
        reinterpret_cast<float4*>(out_max + base)[1] =
            make_float4(res_max[4], res_max[5], res_max[6], res_max[7]);
    }
}

__global__ void __launch_bounds__(256)
ctc_dedup_kernel(const float* __restrict__ idx_f,   // out[0:T]
                 float* __restrict__ keep_f,        // out[T:2T]
                 float* __restrict__ score_f,       // out[2T:3T]: max in, score out
                 int rows)
{
    const int lane = threadIdx.x & 31;
    int i = blockIdx.x * blockDim.x + threadIdx.x;  // float4 index
    int t = i * 4;
    if (t >= rows) return;

    float4 c = reinterpret_cast<const float4*>(idx_f)[i];
    float4 s = reinterpret_cast<const float4*>(score_f)[i];

    // prev for element t: lane-1's c.w covers all lanes except lane 0.
    float prev0 = __shfl_up_sync(FULL_MASK, c.w, 1);
    if (lane == 0) prev0 = (t > 0) ? idx_f[t - 1] : -1.0f;

    bool k0 = (c.x != prev0) && (c.x != (float)BLANK);
    bool k1 = (c.y != c.x)   && (c.y != (float)BLANK);
    bool k2 = (c.z != c.y)   && (c.z != (float)BLANK);
    bool k3 = (c.w != c.z)   && (c.w != (float)BLANK);

    reinterpret_cast<float4*>(keep_f)[i] =
        make_float4(k0 ? 1.0f : 0.0f, k1 ? 1.0f : 0.0f,
                    k2 ? 1.0f : 0.0f, k3 ? 1.0f : 0.0f);
    reinterpret_cast<float4*>(score_f)[i] =
        make_float4(k0 ? s.x : 0.0f, k1 ? s.y : 0.0f,
                    k2 ? s.z : 0.0f, k3 ? s.w : 0.0f);
}

extern "C" void kernel_launch(void* const* d_in, const int* in_sizes, int n_in,
                              void* d_out, int out_size)
{
    const float* em = (const float*)d_in[0];
    float* out = (float*)d_out;

    const int rows = in_sizes[0] / V;            // T = 1048576
    float* out_idx   = out;                      // [0:T)
    float* out_keep  = out + rows;               // [T:2T)
    float* out_score = out + 2 * (size_t)rows;   // [2T:3T)

    {
        dim3 block(WARPS_PER_BLOCK * 32);
        dim3 grid(rows / ROWS_PER_BLOCK);        // exact: 16384
        ctc_argmax_kernel<<<grid, block>>>(em, out_idx, out_score, rows);
    }
    {
        int nvec = rows / 4;                     // 262144
        dim3 block(256);
        dim3 grid(nvec / 256);                   // exact: 1024
        ctc_dedup_kernel<<<grid, block>>>(out_idx, out_keep, out_score, rows);
    }
}